// round 1
// baseline (speedup 1.0000x reference)
#include <cuda_runtime.h>
#include <math_constants.h>
#include <cstdint>

// Problem shape (fixed by the reference)
#define NN 8192
#define DD 512
#define NUM_SRC 8

// GEMM tiling
#define BM 128
#define BN 128
#define BK 32
#define TM 8
#define TN 8
#define NTHREADS 256
#define NCHUNK (NN / BN)   // 64 column chunks

// ---------------- device scratch (no cudaMalloc allowed) ----------------
__device__ float g_m [NCHUNK * NN];   // per-(chunk,row) tile max
__device__ float g_l [NCHUNK * NN];   // per-(chunk,row) sum exp(v - m)
__device__ float g_ms[NCHUNK * NN];   // per-(chunk,row) masked logit sum
__device__ int   g_c [NCHUNK * NN];   // per-(chunk,row) masked count
__device__ int   g_lab[NN];           // normalized int32 labels

// ---------------- label normalization (int32 vs int64 ambiguity) ----------------
// Reference declares int64, but default-JAX demotes to int32. Detect on device:
// if the buffer is int64 little-endian with values in [0,8), the high 32 bits of
// every qword are zero. If it's int32, qword k packs labels (2k, 2k+1) and the
// high word is nonzero with prob 7/8 per qword. Scan 32 qwords (256B, safe for
// either width at N=8192): false-positive prob (1/8)^32 ~ 0.
__global__ void prep_labels(const void* __restrict__ labels_raw) {
    __shared__ int s_is64;
    if (threadIdx.x == 0) {
        const unsigned long long* p = (const unsigned long long*)labels_raw;
        int is64 = 1;
        for (int w = 0; w < 32; w++) {
            if ((p[w] >> 32) != 0ull) { is64 = 0; break; }
        }
        s_is64 = is64;
    }
    __syncthreads();
    const int is64 = s_is64;
    const long long* p64 = (const long long*)labels_raw;
    const int*       p32 = (const int*)labels_raw;
    for (int i = threadIdx.x; i < NN; i += blockDim.x) {
        g_lab[i] = is64 ? (int)p64[i] : p32[i];
    }
}

__global__ void zero_out(float* out) {
    if (threadIdx.x == 0) out[0] = 0.0f;
}

// ---------------- fused GEMM + per-chunk softmax/mask statistics ----------------
// Block (bx, by): computes logits tile [by*128 .. , bx*128 ..] = scale * A @ B^T
// (A = image_features, B = text_features, both row-major [N, D], so this is an
// NT GEMM: C[i][j] = dot(A_row_i, B_row_j)).
// Epilogue: per row of the tile, reduce (max, sumexp, masked_sum, count) across
// the 128 columns and write to scratch[bx][global_row].
__global__ void __launch_bounds__(NTHREADS, 2)
gemm_partial(const float* __restrict__ A, const float* __restrict__ B,
             const float* __restrict__ scale_p)
{
    __shared__ __align__(16) float As[BK][BM];   // k-major for vectorized LDS
    __shared__ __align__(16) float Bs[BK][BN];
    __shared__ int labB[BN];

    const int bx = blockIdx.x;      // column tile / chunk index
    const int by = blockIdx.y;      // row tile
    const int tid = threadIdx.x;
    const int tx = tid & 15;        // 16 threads span 128 cols (8 each)
    const int ty = tid >> 4;        // 16 thread-rows span 128 rows (8 each)

    if (tid < BN) labB[tid] = g_lab[bx * BN + tid];

    const float* Ab = A + (size_t)by * BM * DD;
    const float* Bb = B + (size_t)bx * BN * DD;
    const int lrow = tid >> 1;          // 0..127
    const int kq   = (tid & 1) << 4;    // 0 or 16

    float acc[TM][TN];
    #pragma unroll
    for (int i = 0; i < TM; i++)
        #pragma unroll
        for (int j = 0; j < TN; j++) acc[i][j] = 0.0f;

    for (int k0 = 0; k0 < DD; k0 += BK) {
        // cooperative loads: each thread moves 16 contiguous floats per matrix,
        // stored k-major (transposed) into smem
        #pragma unroll
        for (int v = 0; v < 4; v++) {
            const float4 fa = *(const float4*)(Ab + (size_t)lrow * DD + k0 + kq + v * 4);
            const float4 fb = *(const float4*)(Bb + (size_t)lrow * DD + k0 + kq + v * 4);
            const int kb = kq + v * 4;
            As[kb + 0][lrow] = fa.x; As[kb + 1][lrow] = fa.y;
            As[kb + 2][lrow] = fa.z; As[kb + 3][lrow] = fa.w;
            Bs[kb + 0][lrow] = fb.x; Bs[kb + 1][lrow] = fb.y;
            Bs[kb + 2][lrow] = fb.z; Bs[kb + 3][lrow] = fb.w;
        }
        __syncthreads();

        #pragma unroll 8
        for (int kk = 0; kk < BK; kk++) {
            float a[TM], b[TN];
            *(float4*)&a[0] = *(const float4*)&As[kk][ty * TM];
            *(float4*)&a[4] = *(const float4*)&As[kk][ty * TM + 4];
            *(float4*)&b[0] = *(const float4*)&Bs[kk][tx * TN];
            *(float4*)&b[4] = *(const float4*)&Bs[kk][tx * TN + 4];
            #pragma unroll
            for (int i = 0; i < TM; i++)
                #pragma unroll
                for (int j = 0; j < TN; j++)
                    acc[i][j] = fmaf(a[i], b[j], acc[i][j]);
        }
        __syncthreads();
    }

    // ---------------- fused epilogue ----------------
    const float s = *scale_p;
    const int gx0 = bx * BN + tx * TN;

    #pragma unroll
    for (int i = 0; i < TM; i++) {
        const int gy = by * BM + ty * TM + i;
        const int labr = g_lab[gy];

        float v[TN];
        float m = -CUDART_INF_F;
        #pragma unroll
        for (int j = 0; j < TN; j++) {
            v[j] = acc[i][j] * s;
            m = fmaxf(m, v[j]);
        }
        // reduce across the 16 lanes (tx) covering this row's 128 columns.
        // tx = lane & 15, so xor over bits 0..3 stays within the row group.
        #pragma unroll
        for (int o = 8; o >= 1; o >>= 1)
            m = fmaxf(m, __shfl_xor_sync(0xffffffffu, m, o));

        float l = 0.0f, ms = 0.0f;
        int c = 0;
        #pragma unroll
        for (int j = 0; j < TN; j++) {
            l += __expf(v[j] - m);
            const int gx = gx0 + j;
            if (labB[tx * TN + j] == labr && gx != gy) { ms += v[j]; c++; }
        }
        #pragma unroll
        for (int o = 8; o >= 1; o >>= 1) {
            l  += __shfl_xor_sync(0xffffffffu, l,  o);
            ms += __shfl_xor_sync(0xffffffffu, ms, o);
            c  += __shfl_xor_sync(0xffffffffu, c,  o);
        }
        if (tx == 0) {
            const int idx = bx * NN + gy;
            g_m[idx] = m; g_l[idx] = l; g_ms[idx] = ms; g_c[idx] = c;
        }
    }
}

// ---------------- chunk merge + final loss ----------------
__global__ void reduce_rows(float* __restrict__ out)
{
    const int row = blockIdx.x * blockDim.x + threadIdx.x;  // 0..8191

    float M = -CUDART_INF_F;
    #pragma unroll 8
    for (int c = 0; c < NCHUNK; c++)
        M = fmaxf(M, g_m[c * NN + row]);

    float L = 0.0f, MS = 0.0f;
    int   C = 0;
    #pragma unroll 8
    for (int c = 0; c < NCHUNK; c++) {
        L  += g_l[c * NN + row] * __expf(g_m[c * NN + row] - M);
        MS += g_ms[c * NN + row];
        C  += g_c[c * NN + row];
    }
    const float lse = M + logf(L);
    float val = (C > 0) ? (MS / (float)C - lse) : 0.0f;

    // block reduction then one atomic per block
    #pragma unroll
    for (int o = 16; o >= 1; o >>= 1)
        val += __shfl_xor_sync(0xffffffffu, val, o);

    __shared__ float sred[8];
    const int warp = threadIdx.x >> 5;
    if ((threadIdx.x & 31) == 0) sred[warp] = val;
    __syncthreads();
    if (threadIdx.x == 0) {
        float t = 0.0f;
        #pragma unroll
        for (int w = 0; w < 8; w++) t += sred[w];
        atomicAdd(out, -t / (float)NN);
    }
}

// ---------------- launch ----------------
extern "C" void kernel_launch(void* const* d_in, const int* in_sizes, int n_in,
                              void* d_out, int out_size)
{
    const float* image = (const float*)d_in[0];
    const float* text  = (const float*)d_in[1];
    const float* scale = (const float*)d_in[2];
    const void*  labels = d_in[3];
    float* out = (float*)d_out;

    prep_labels<<<1, 256>>>(labels);
    zero_out<<<1, 32>>>(out);

    dim3 grid(NCHUNK, NN / BM);       // 64 x 64 tiles
    gemm_partial<<<grid, NTHREADS>>>(image, text, scale);

    reduce_rows<<<NN / 256, 256>>>(out);
}

// round 3
// speedup vs baseline: 2.2728x; 2.2728x over previous
#include <cuda_runtime.h>
#include <cuda_bf16.h>
#include <math_constants.h>
#include <cstdint>

// Problem shape (fixed by the reference)
#define NN 8192
#define DD 512

// GEMM tiling
#define BM 128
#define BN 128
#define BK 32                 // bf16 elements per k-iter
#define NKITER (DD / BK)      // 16
#define NTHREADS 256
#define NSTAGE 4
#define NCHUNK 256            // stats chunk width = 32 cols

// smem stage layout: 4 tiles of 128 rows x 80 bytes (64B data + 16B pad)
#define ROWB 80
#define TILE_B (128 * ROWB)       // 10240
#define S_AHI 0
#define S_ALO 10240
#define S_BHI 20480
#define S_BLO 30720
#define STAGE_B (4 * TILE_B)      // 40960
#define SMEM_LAB_A 0              // 128 ints (row labels)
#define SMEM_LAB_B 512            // 128 ints (col labels)
#define SMEM_STAGE0 1024
#define SMEM_TOTAL (SMEM_STAGE0 + NSTAGE * STAGE_B)   // 164864

// ---------------- device scratch (no cudaMalloc allowed) ----------------
__device__ __nv_bfloat16 gAhi[NN * DD];
__device__ __nv_bfloat16 gAlo[NN * DD];
__device__ __nv_bfloat16 gBhi[NN * DD];
__device__ __nv_bfloat16 gBlo[NN * DD];
__device__ float g_m [NCHUNK * NN];
__device__ float g_l [NCHUNK * NN];
__device__ float g_ms[NCHUNK * NN];
__device__ int   g_c [NCHUNK * NN];
__device__ int   g_lab[NN];

// ---------------- PTX helpers (baseline sm_80+ features only) ----------------
__device__ __forceinline__ uint32_t smem_u32(const void* p) {
    uint32_t a;
    asm("{ .reg .u64 t; cvta.to.shared.u64 t, %1; cvt.u32.u64 %0, t; }" : "=r"(a) : "l"(p));
    return a;
}
#define CPA16(dst, src) \
    asm volatile("cp.async.cg.shared.global [%0], [%1], 16;" :: "r"(dst), "l"(src))
#define CPA_COMMIT() asm volatile("cp.async.commit_group;" ::: "memory")
#define CPA_WAIT(n)  asm volatile("cp.async.wait_group %0;" :: "n"(n) : "memory")

__device__ __forceinline__ void ldsm4(uint32_t (&r)[4], uint32_t addr) {
    asm volatile("ldmatrix.sync.aligned.m8n8.x4.shared.b16 {%0,%1,%2,%3}, [%4];"
                 : "=r"(r[0]), "=r"(r[1]), "=r"(r[2]), "=r"(r[3]) : "r"(addr));
}
__device__ __forceinline__ void mma_bf16(float (&c)[4], const uint32_t (&a)[4],
                                         uint32_t b0, uint32_t b1) {
    asm volatile(
        "mma.sync.aligned.m16n8k16.row.col.f32.bf16.bf16.f32 "
        "{%0,%1,%2,%3}, {%4,%5,%6,%7}, {%8,%9}, {%0,%1,%2,%3};"
        : "+f"(c[0]), "+f"(c[1]), "+f"(c[2]), "+f"(c[3])
        : "r"(a[0]), "r"(a[1]), "r"(a[2]), "r"(a[3]), "r"(b0), "r"(b1));
}

// ---------------- label normalization (int32 vs int64 ambiguity) ----------------
__global__ void prep_labels(const void* __restrict__ labels_raw) {
    __shared__ int s_is64;
    if (threadIdx.x == 0) {
        const unsigned long long* p = (const unsigned long long*)labels_raw;
        int is64 = 1;
        for (int w = 0; w < 32; w++)
            if ((p[w] >> 32) != 0ull) { is64 = 0; break; }
        s_is64 = is64;
    }
    __syncthreads();
    const int is64 = s_is64;
    const long long* p64 = (const long long*)labels_raw;
    const int*       p32 = (const int*)labels_raw;
    for (int i = threadIdx.x; i < NN; i += blockDim.x)
        g_lab[i] = is64 ? (int)p64[i] : p32[i];
}

__global__ void zero_out(float* out) { if (threadIdx.x == 0) out[0] = 0.0f; }

// ---------------- fp32 -> bf16 hi/lo split ----------------
__global__ void split_bf16(const float* __restrict__ A, const float* __restrict__ B) {
    const int base = blockIdx.x * 256 + threadIdx.x;   // grid 2048 x 256
    #pragma unroll
    for (int i = 0; i < 4; i++) {
        int e = base + i * 524288;
        const float4* src;
        __nv_bfloat16 *hi, *lo;
        int off;
        if (e < 1048576) { src = (const float4*)A; off = e;           hi = gAhi; lo = gAlo; }
        else             { src = (const float4*)B; off = e - 1048576; hi = gBhi; lo = gBlo; }
        const float4 v = src[off];
        __nv_bfloat16 h0 = __float2bfloat16_rn(v.x);
        __nv_bfloat16 h1 = __float2bfloat16_rn(v.y);
        __nv_bfloat16 h2 = __float2bfloat16_rn(v.z);
        __nv_bfloat16 h3 = __float2bfloat16_rn(v.w);
        __nv_bfloat16 l0 = __float2bfloat16_rn(v.x - __bfloat162float(h0));
        __nv_bfloat16 l1 = __float2bfloat16_rn(v.y - __bfloat162float(h1));
        __nv_bfloat16 l2 = __float2bfloat16_rn(v.z - __bfloat162float(h2));
        __nv_bfloat16 l3 = __float2bfloat16_rn(v.w - __bfloat162float(h3));
        ((__nv_bfloat162*)hi)[off * 2 + 0] = __nv_bfloat162(h0, h1);
        ((__nv_bfloat162*)hi)[off * 2 + 1] = __nv_bfloat162(h2, h3);
        ((__nv_bfloat162*)lo)[off * 2 + 0] = __nv_bfloat162(l0, l1);
        ((__nv_bfloat162*)lo)[off * 2 + 1] = __nv_bfloat162(l2, l3);
    }
}

// ---------------- GEMM building blocks ----------------
__device__ __forceinline__ void load_stage(uint32_t sbase, int slot, int ki,
                                           int by, int bx, int tid) {
    const uint32_t stg = sbase + SMEM_STAGE0 + slot * STAGE_B;
    const int kb = ki * 64;           // byte offset within a 1024B feature row
    #pragma unroll
    for (int j = 0; j < 2; j++) {
        const int c = tid + j * 256;  // 512 chunks of 16B per tile
        const int r = c >> 2, q = c & 3;
        const uint32_t so = (uint32_t)(r * ROWB + q * 16);
        const size_t gA = (size_t)(by * BM + r) * 1024 + kb + q * 16;
        const size_t gB = (size_t)(bx * BN + r) * 1024 + kb + q * 16;
        CPA16(stg + S_AHI + so, (const char*)gAhi + gA);
        CPA16(stg + S_ALO + so, (const char*)gAlo + gA);
        CPA16(stg + S_BHI + so, (const char*)gBhi + gB);
        CPA16(stg + S_BLO + so, (const char*)gBlo + gB);
    }
}

__device__ __forceinline__ void compute_stage(uint32_t stg, int wm, int wn, int lane,
                                              float (&acc)[4][4][4]) {
    #pragma unroll
    for (int ks = 0; ks < 2; ks++) {
        uint32_t ah[4][4], al[4][4], bh[2][4], bl[2][4];
        const uint32_t a_lane = (uint32_t)((wm * 64 + (lane & 15)) * ROWB +
                                           ((lane >> 4) << 4) + ks * 32);
        #pragma unroll
        for (int mt = 0; mt < 4; mt++) {
            const uint32_t ad = stg + S_AHI + a_lane + mt * 16 * ROWB;
            ldsm4(ah[mt], ad);
            ldsm4(al[mt], ad + (S_ALO - S_AHI));
        }
        const uint32_t b_lane = (uint32_t)((wn * 32 + ((lane >> 4) & 1) * 8 + (lane & 7)) * ROWB +
                                           (((lane >> 3) & 1) << 4) + ks * 32);
        #pragma unroll
        for (int ntp = 0; ntp < 2; ntp++) {
            const uint32_t bd = stg + S_BHI + b_lane + ntp * 16 * ROWB;
            ldsm4(bh[ntp], bd);
            ldsm4(bl[ntp], bd + (S_BLO - S_BHI));
        }
        #pragma unroll
        for (int mt = 0; mt < 4; mt++)
            #pragma unroll
            for (int nt = 0; nt < 4; nt++) {
                const int ntp = nt >> 1, s2 = (nt & 1) * 2;
                mma_bf16(acc[mt][nt], ah[mt], bh[ntp][s2], bh[ntp][s2 + 1]);
                mma_bf16(acc[mt][nt], ah[mt], bl[ntp][s2], bl[ntp][s2 + 1]);
                mma_bf16(acc[mt][nt], al[mt], bh[ntp][s2], bh[ntp][s2 + 1]);
            }
    }
}

// ---------------- fused GEMM + stats ----------------
__global__ void __launch_bounds__(NTHREADS, 1)
gemm_mma(const float* __restrict__ scale_p)
{
    extern __shared__ char smem[];
    const uint32_t sbase = smem_u32(smem);
    const int tid = threadIdx.x;
    const int wid = tid >> 5, lane = tid & 31;
    const int wm = wid >> 2, wn = wid & 3;
    const int bx = blockIdx.x, by = blockIdx.y;

    int* labA = (int*)(smem + SMEM_LAB_A);
    int* labB = (int*)(smem + SMEM_LAB_B);
    if (tid < 128)       labA[tid] = g_lab[by * BM + tid];
    else                 labB[tid - 128] = g_lab[bx * BN + (tid - 128)];

    // prologue: 3 stages in flight
    load_stage(sbase, 0, 0, by, bx, tid); CPA_COMMIT();
    load_stage(sbase, 1, 1, by, bx, tid); CPA_COMMIT();
    load_stage(sbase, 2, 2, by, bx, tid); CPA_COMMIT();

    float acc[4][4][4];
    #pragma unroll
    for (int a = 0; a < 4; a++)
        #pragma unroll
        for (int b = 0; b < 4; b++)
            #pragma unroll
            for (int e = 0; e < 4; e++) acc[a][b][e] = 0.0f;

    #pragma unroll 1
    for (int i = 0; i < NKITER; i++) {
        if (i <= NKITER - 3)      CPA_WAIT(2);
        else if (i == NKITER - 2) CPA_WAIT(1);
        else                      CPA_WAIT(0);
        __syncthreads();
        if (i + 3 < NKITER) { load_stage(sbase, (i + 3) & 3, i + 3, by, bx, tid); CPA_COMMIT(); }
        compute_stage(sbase + SMEM_STAGE0 + (i & 3) * STAGE_B, wm, wn, lane, acc);
    }

    // ---------------- epilogue: per-row stats over this warp's 32 columns ----------------
    const float s = *scale_p;
    const int chunk = bx * 4 + wn;
    const int colb = bx * BN + wn * 32 + (lane & 3) * 2;   // this lane's first global col

    #pragma unroll
    for (int mt = 0; mt < 4; mt++) {
        #pragma unroll
        for (int half = 0; half < 2; half++) {
            const int rloc = wm * 64 + mt * 16 + (lane >> 2) + half * 8;
            const int gy = by * BM + rloc;
            const int labr = labA[rloc];

            float v[8];
            #pragma unroll
            for (int nt = 0; nt < 4; nt++) {
                v[nt * 2 + 0] = acc[mt][nt][half * 2 + 0] * s;
                v[nt * 2 + 1] = acc[mt][nt][half * 2 + 1] * s;
            }
            float m = v[0];
            #pragma unroll
            for (int j = 1; j < 8; j++) m = fmaxf(m, v[j]);
            m = fmaxf(m, __shfl_xor_sync(0xffffffffu, m, 1));
            m = fmaxf(m, __shfl_xor_sync(0xffffffffu, m, 2));

            float l = 0.0f, msum = 0.0f;
            int cnt = 0;
            #pragma unroll
            for (int j = 0; j < 8; j++) {
                l += __expf(v[j] - m);
                const int gx = colb + (j >> 1) * 8 + (j & 1);
                const int cloc = wn * 32 + (j >> 1) * 8 + (lane & 3) * 2 + (j & 1);
                if (labB[cloc] == labr && gx != gy) { msum += v[j]; cnt++; }
            }
            l    += __shfl_xor_sync(0xffffffffu, l, 1);
            l    += __shfl_xor_sync(0xffffffffu, l, 2);
            msum += __shfl_xor_sync(0xffffffffu, msum, 1);
            msum += __shfl_xor_sync(0xffffffffu, msum, 2);
            cnt  += __shfl_xor_sync(0xffffffffu, cnt, 1);
            cnt  += __shfl_xor_sync(0xffffffffu, cnt, 2);

            if ((lane & 3) == 0) {
                const int idx = chunk * NN + gy;
                g_m[idx] = m; g_l[idx] = l; g_ms[idx] = msum; g_c[idx] = cnt;
            }
        }
    }
}

// ---------------- chunk merge + final loss ----------------
__global__ void reduce_rows(float* __restrict__ out)
{
    const int t = blockIdx.x * 256 + threadIdx.x;   // 65536 threads
    const int row = t >> 3;
    const int sub = t & 7;                          // 8 lanes per row, 32 chunks each
    const int c0 = sub * 32;

    float M = -CUDART_INF_F;
    #pragma unroll 8
    for (int c = 0; c < 32; c++)
        M = fmaxf(M, g_m[(c0 + c) * NN + row]);
    #pragma unroll
    for (int o = 1; o <= 4; o <<= 1)
        M = fmaxf(M, __shfl_xor_sync(0xffffffffu, M, o));

    float L = 0.0f, MS = 0.0f;
    int C = 0;
    #pragma unroll 8
    for (int c = 0; c < 32; c++) {
        const int i = (c0 + c) * NN + row;
        L  += g_l[i] * __expf(g_m[i] - M);
        MS += g_ms[i];
        C  += g_c[i];
    }
    #pragma unroll
    for (int o = 1; o <= 4; o <<= 1) {
        L  += __shfl_xor_sync(0xffffffffu, L,  o);
        MS += __shfl_xor_sync(0xffffffffu, MS, o);
        C  += __shfl_xor_sync(0xffffffffu, C,  o);
    }

    float val = 0.0f;
    if (sub == 0) {
        const float lse = M + logf(L);
        val = (C > 0) ? (MS / (float)C - lse) : 0.0f;
    }
    #pragma unroll
    for (int o = 16; o >= 1; o >>= 1)
        val += __shfl_xor_sync(0xffffffffu, val, o);

    __shared__ float sred[8];
    if ((threadIdx.x & 31) == 0) sred[threadIdx.x >> 5] = val;
    __syncthreads();
    if (threadIdx.x == 0) {
        float tsum = 0.0f;
        #pragma unroll
        for (int w = 0; w < 8; w++) tsum += sred[w];
        atomicAdd(out, -tsum / (float)NN);
    }
}

// ---------------- launch ----------------
extern "C" void kernel_launch(void* const* d_in, const int* in_sizes, int n_in,
                              void* d_out, int out_size)
{
    const float* image  = (const float*)d_in[0];
    const float* text   = (const float*)d_in[1];
    const float* scale  = (const float*)d_in[2];
    const void*  labels = d_in[3];
    float* out = (float*)d_out;

    cudaFuncSetAttribute(gemm_mma, cudaFuncAttributeMaxDynamicSharedMemorySize, SMEM_TOTAL);

    prep_labels<<<1, 256>>>(labels);
    zero_out<<<1, 32>>>(out);
    split_bf16<<<2048, 256>>>(image, text);

    dim3 grid(NN / BN, NN / BM);   // 64 x 64 tiles
    gemm_mma<<<grid, NTHREADS, SMEM_TOTAL>>>(scale);

    reduce_rows<<<256, 256>>>(out);
}

// round 4
// speedup vs baseline: 2.3332x; 1.0266x over previous
#include <cuda_runtime.h>
#include <cuda_bf16.h>
#include <math_constants.h>
#include <cstdint>

// Problem shape (fixed by the reference)
#define NN 8192
#define DD 512

// GEMM tiling
#define BM 128
#define BN 128
#define BK 64                 // bf16 elements per smem stage
#define NKITER (DD / BK)      // 8
#define NTHREADS 512
#define NCHUNK 256            // stats chunk width = 32 cols

// smem: 2 stages of 4 tiles, each 128 rows x 144 bytes (128B data + 16B pad)
#define ROWB 144
#define TILE_B (128 * ROWB)        // 18432
#define S_AHI 0
#define S_ALO TILE_B
#define S_BHI (2 * TILE_B)
#define S_BLO (3 * TILE_B)
#define STAGE_B (4 * TILE_B)       // 73728
#define SMEM_LAB_A 0               // 128 ints
#define SMEM_LAB_B 512             // 128 ints
#define SMEM_STAGE0 1024
#define SMEM_TOTAL (SMEM_STAGE0 + 2 * STAGE_B)   // 148480

// ---------------- device scratch (no cudaMalloc allowed) ----------------
__device__ __nv_bfloat16 gAhi[NN * DD];
__device__ __nv_bfloat16 gAlo[NN * DD];
__device__ __nv_bfloat16 gBhi[NN * DD];
__device__ __nv_bfloat16 gBlo[NN * DD];
__device__ float g_m [NCHUNK * NN];
__device__ float g_l [NCHUNK * NN];
__device__ float g_ms[NCHUNK * NN];
__device__ int   g_c [NCHUNK * NN];
__device__ int   g_lab[NN];

// ---------------- PTX helpers (baseline sm_80+ features only) ----------------
__device__ __forceinline__ uint32_t smem_u32(const void* p) {
    uint32_t a;
    asm("{ .reg .u64 t; cvta.to.shared.u64 t, %1; cvt.u32.u64 %0, t; }" : "=r"(a) : "l"(p));
    return a;
}
#define CPA16(dst, src) \
    asm volatile("cp.async.cg.shared.global [%0], [%1], 16;" :: "r"(dst), "l"(src))
#define CPA_COMMIT() asm volatile("cp.async.commit_group;" ::: "memory")
#define CPA_WAIT(n)  asm volatile("cp.async.wait_group %0;" :: "n"(n) : "memory")

__device__ __forceinline__ void ldsm4(uint32_t (&r)[4], uint32_t addr) {
    asm volatile("ldmatrix.sync.aligned.m8n8.x4.shared.b16 {%0,%1,%2,%3}, [%4];"
                 : "=r"(r[0]), "=r"(r[1]), "=r"(r[2]), "=r"(r[3]) : "r"(addr));
}
__device__ __forceinline__ void mma_bf16(float (&c)[4], const uint32_t (&a)[4],
                                         uint32_t b0, uint32_t b1) {
    asm volatile(
        "mma.sync.aligned.m16n8k16.row.col.f32.bf16.bf16.f32 "
        "{%0,%1,%2,%3}, {%4,%5,%6,%7}, {%8,%9}, {%0,%1,%2,%3};"
        : "+f"(c[0]), "+f"(c[1]), "+f"(c[2]), "+f"(c[3])
        : "r"(a[0]), "r"(a[1]), "r"(a[2]), "r"(a[3]), "r"(b0), "r"(b1));
}

// ---------------- label normalization (int32 vs int64 ambiguity) ----------------
__global__ void prep_labels(const void* __restrict__ labels_raw) {
    __shared__ int s_is64;
    if (threadIdx.x == 0) {
        const unsigned long long* p = (const unsigned long long*)labels_raw;
        int is64 = 1;
        for (int w = 0; w < 32; w++)
            if ((p[w] >> 32) != 0ull) { is64 = 0; break; }
        s_is64 = is64;
    }
    __syncthreads();
    const int is64 = s_is64;
    const long long* p64 = (const long long*)labels_raw;
    const int*       p32 = (const int*)labels_raw;
    for (int i = threadIdx.x; i < NN; i += blockDim.x)
        g_lab[i] = is64 ? (int)p64[i] : p32[i];
}

__global__ void zero_out(float* out) { if (threadIdx.x == 0) out[0] = 0.0f; }

// ---------------- fp32 -> bf16 hi/lo split ----------------
__global__ void split_bf16(const float* __restrict__ A, const float* __restrict__ B) {
    const int base = blockIdx.x * 256 + threadIdx.x;   // grid 2048 x 256
    #pragma unroll
    for (int i = 0; i < 4; i++) {
        int e = base + i * 524288;
        const float4* src;
        __nv_bfloat16 *hi, *lo;
        int off;
        if (e < 1048576) { src = (const float4*)A; off = e;           hi = gAhi; lo = gAlo; }
        else             { src = (const float4*)B; off = e - 1048576; hi = gBhi; lo = gBlo; }
        const float4 v = src[off];
        __nv_bfloat16 h0 = __float2bfloat16_rn(v.x);
        __nv_bfloat16 h1 = __float2bfloat16_rn(v.y);
        __nv_bfloat16 h2 = __float2bfloat16_rn(v.z);
        __nv_bfloat16 h3 = __float2bfloat16_rn(v.w);
        __nv_bfloat16 l0 = __float2bfloat16_rn(v.x - __bfloat162float(h0));
        __nv_bfloat16 l1 = __float2bfloat16_rn(v.y - __bfloat162float(h1));
        __nv_bfloat16 l2 = __float2bfloat16_rn(v.z - __bfloat162float(h2));
        __nv_bfloat16 l3 = __float2bfloat16_rn(v.w - __bfloat162float(h3));
        ((__nv_bfloat162*)hi)[off * 2 + 0] = __nv_bfloat162(h0, h1);
        ((__nv_bfloat162*)hi)[off * 2 + 1] = __nv_bfloat162(h2, h3);
        ((__nv_bfloat162*)lo)[off * 2 + 0] = __nv_bfloat162(l0, l1);
        ((__nv_bfloat162*)lo)[off * 2 + 1] = __nv_bfloat162(l2, l3);
    }
}

// ---------------- GEMM building blocks ----------------
// Stage load: 4 tiles of 128 rows x 128B. 1024 x 16B chunks per tile,
// 512 threads -> 2 chunks per thread per tile.
__device__ __forceinline__ void load_stage(uint32_t sbase, int slot, int ki,
                                           int by, int bx, int tid) {
    const uint32_t stg = sbase + SMEM_STAGE0 + slot * STAGE_B;
    const int kb = ki * 128;          // byte offset within a 1024B feature row
    #pragma unroll
    for (int j = 0; j < 2; j++) {
        const int c = tid + j * 512;  // 0..1023
        const int r = c >> 3, q = c & 7;
        const uint32_t so = (uint32_t)(r * ROWB + q * 16);
        const size_t gA = (size_t)(by * BM + r) * 1024 + kb + q * 16;
        const size_t gB = (size_t)(bx * BN + r) * 1024 + kb + q * 16;
        CPA16(stg + S_AHI + so, (const char*)gAhi + gA);
        CPA16(stg + S_ALO + so, (const char*)gAlo + gA);
        CPA16(stg + S_BHI + so, (const char*)gBhi + gB);
        CPA16(stg + S_BLO + so, (const char*)gBlo + gB);
    }
}

// Warp tile 32(M) x 32(N); 4 k16-steps per stage.
__device__ __forceinline__ void compute_stage(uint32_t stg, int wm, int wn, int lane,
                                              float (&acc)[2][4][4]) {
    #pragma unroll
    for (int ks = 0; ks < 4; ks++) {
        uint32_t ah[2][4], al[2][4], bh[2][4], bl[2][4];
        const uint32_t a_lane = (uint32_t)((wm * 32 + (lane & 15)) * ROWB +
                                           ((lane >> 4) << 4) + ks * 32);
        #pragma unroll
        for (int mt = 0; mt < 2; mt++) {
            const uint32_t ad = stg + S_AHI + a_lane + mt * 16 * ROWB;
            ldsm4(ah[mt], ad);
            ldsm4(al[mt], ad + (S_ALO - S_AHI));
        }
        const uint32_t b_lane = (uint32_t)((wn * 32 + ((lane >> 4) & 1) * 8 + (lane & 7)) * ROWB +
                                           (((lane >> 3) & 1) << 4) + ks * 32);
        #pragma unroll
        for (int ntp = 0; ntp < 2; ntp++) {
            const uint32_t bd = stg + S_BHI + b_lane + ntp * 16 * ROWB;
            ldsm4(bh[ntp], bd);
            ldsm4(bl[ntp], bd + (S_BLO - S_BHI));
        }
        #pragma unroll
        for (int mt = 0; mt < 2; mt++)
            #pragma unroll
            for (int nt = 0; nt < 4; nt++) {
                const int ntp = nt >> 1, s2 = (nt & 1) * 2;
                mma_bf16(acc[mt][nt], ah[mt], bh[ntp][s2], bh[ntp][s2 + 1]);
                mma_bf16(acc[mt][nt], ah[mt], bl[ntp][s2], bl[ntp][s2 + 1]);
                mma_bf16(acc[mt][nt], al[mt], bh[ntp][s2], bh[ntp][s2 + 1]);
            }
    }
}

// ---------------- fused GEMM + stats ----------------
__global__ void __launch_bounds__(NTHREADS, 1)
gemm_mma(const float* __restrict__ scale_p)
{
    extern __shared__ char smem[];
    const uint32_t sbase = smem_u32(smem);
    const int tid = threadIdx.x;
    const int wid = tid >> 5, lane = tid & 31;
    const int wm = wid >> 2, wn = wid & 3;      // 4x4 warp grid, tile 32x32
    const int bx = blockIdx.x, by = blockIdx.y;

    int* labA = (int*)(smem + SMEM_LAB_A);
    int* labB = (int*)(smem + SMEM_LAB_B);
    if (tid < 128)                     labA[tid] = g_lab[by * BM + tid];
    else if (tid < 256)                labB[tid - 128] = g_lab[bx * BN + (tid - 128)];

    // prologue: both stages in flight
    load_stage(sbase, 0, 0, by, bx, tid); CPA_COMMIT();
    load_stage(sbase, 1, 1, by, bx, tid); CPA_COMMIT();

    float acc[2][4][4];
    #pragma unroll
    for (int a = 0; a < 2; a++)
        #pragma unroll
        for (int b = 0; b < 4; b++)
            #pragma unroll
            for (int e = 0; e < 4; e++) acc[a][b][e] = 0.0f;

    #pragma unroll 1
    for (int i = 0; i < NKITER; i++) {
        if (i < NKITER - 1) CPA_WAIT(1);
        else                CPA_WAIT(0);
        __syncthreads();
        compute_stage(sbase + SMEM_STAGE0 + (i & 1) * STAGE_B, wm, wn, lane, acc);
        __syncthreads();
        if (i + 2 < NKITER) { load_stage(sbase, i & 1, i + 2, by, bx, tid); CPA_COMMIT(); }
    }

    // ---------------- epilogue: per-row stats over this warp's 32 columns ----------------
    const float s = *scale_p;
    const int chunk = bx * 4 + wn;
    const int colb = bx * BN + wn * 32 + (lane & 3) * 2;

    #pragma unroll
    for (int mt = 0; mt < 2; mt++) {
        #pragma unroll
        for (int half = 0; half < 2; half++) {
            const int rloc = wm * 32 + mt * 16 + (lane >> 2) + half * 8;
            const int gy = by * BM + rloc;
            const int labr = labA[rloc];

            float v[8];
            #pragma unroll
            for (int nt = 0; nt < 4; nt++) {
                v[nt * 2 + 0] = acc[mt][nt][half * 2 + 0] * s;
                v[nt * 2 + 1] = acc[mt][nt][half * 2 + 1] * s;
            }
            float m = v[0];
            #pragma unroll
            for (int j = 1; j < 8; j++) m = fmaxf(m, v[j]);
            m = fmaxf(m, __shfl_xor_sync(0xffffffffu, m, 1));
            m = fmaxf(m, __shfl_xor_sync(0xffffffffu, m, 2));

            float l = 0.0f, msum = 0.0f;
            int cnt = 0;
            #pragma unroll
            for (int j = 0; j < 8; j++) {
                l += __expf(v[j] - m);
                const int gx = colb + (j >> 1) * 8 + (j & 1);
                const int cloc = wn * 32 + (j >> 1) * 8 + (lane & 3) * 2 + (j & 1);
                if (labB[cloc] == labr && gx != gy) { msum += v[j]; cnt++; }
            }
            l    += __shfl_xor_sync(0xffffffffu, l, 1);
            l    += __shfl_xor_sync(0xffffffffu, l, 2);
            msum += __shfl_xor_sync(0xffffffffu, msum, 1);
            msum += __shfl_xor_sync(0xffffffffu, msum, 2);
            cnt  += __shfl_xor_sync(0xffffffffu, cnt, 1);
            cnt  += __shfl_xor_sync(0xffffffffu, cnt, 2);

            if ((lane & 3) == 0) {
                const int idx = chunk * NN + gy;
                g_m[idx] = m; g_l[idx] = l; g_ms[idx] = msum; g_c[idx] = cnt;
            }
        }
    }
}

// ---------------- chunk merge + final loss ----------------
__global__ void reduce_rows(float* __restrict__ out)
{
    const int t = blockIdx.x * 256 + threadIdx.x;   // 65536 threads
    const int row = t >> 3;
    const int sub = t & 7;                          // 8 lanes per row, 32 chunks each
    const int c0 = sub * 32;

    float M = -CUDART_INF_F;
    #pragma unroll 8
    for (int c = 0; c < 32; c++)
        M = fmaxf(M, g_m[(c0 + c) * NN + row]);
    #pragma unroll
    for (int o = 1; o <= 4; o <<= 1)
        M = fmaxf(M, __shfl_xor_sync(0xffffffffu, M, o));

    float L = 0.0f, MS = 0.0f;
    int C = 0;
    #pragma unroll 8
    for (int c = 0; c < 32; c++) {
        const int i = (c0 + c) * NN + row;
        L  += g_l[i] * __expf(g_m[i] - M);
        MS += g_ms[i];
        C  += g_c[i];
    }
    #pragma unroll
    for (int o = 1; o <= 4; o <<= 1) {
        L  += __shfl_xor_sync(0xffffffffu, L,  o);
        MS += __shfl_xor_sync(0xffffffffu, MS, o);
        C  += __shfl_xor_sync(0xffffffffu, C,  o);
    }

    float val = 0.0f;
    if (sub == 0) {
        const float lse = M + logf(L);
        val = (C > 0) ? (MS / (float)C - lse) : 0.0f;
    }
    #pragma unroll
    for (int o = 16; o >= 1; o >>= 1)
        val += __shfl_xor_sync(0xffffffffu, val, o);

    __shared__ float sred[8];
    if ((threadIdx.x & 31) == 0) sred[threadIdx.x >> 5] = val;
    __syncthreads();
    if (threadIdx.x == 0) {
        float tsum = 0.0f;
        #pragma unroll
        for (int w = 0; w < 8; w++) tsum += sred[w];
        atomicAdd(out, -tsum / (float)NN);
    }
}

// ---------------- launch ----------------
extern "C" void kernel_launch(void* const* d_in, const int* in_sizes, int n_in,
                              void* d_out, int out_size)
{
    const float* image  = (const float*)d_in[0];
    const float* text   = (const float*)d_in[1];
    const float* scale  = (const float*)d_in[2];
    const void*  labels = d_in[3];
    float* out = (float*)d_out;

    cudaFuncSetAttribute(gemm_mma, cudaFuncAttributeMaxDynamicSharedMemorySize, SMEM_TOTAL);

    prep_labels<<<1, 256>>>(labels);
    zero_out<<<1, 32>>>(out);
    split_bf16<<<2048, 256>>>(image, text);

    dim3 grid(NN / BN, NN / BM);   // 64 x 64 tiles
    gemm_mma<<<grid, NTHREADS, SMEM_TOTAL>>>(scale);

    reduce_rows<<<256, 256>>>(out);
}

// round 5
// speedup vs baseline: 2.4999x; 1.0714x over previous
#include <cuda_runtime.h>
#include <cuda_bf16.h>
#include <math_constants.h>
#include <cstdint>

// Problem shape (fixed by the reference)
#define NN 8192
#define DD 512

// GEMM tiling
#define BM 128
#define BN 128
#define BK 64                 // bf16 elements per smem stage
#define NKITER (DD / BK)      // 8
#define NTHREADS 512
#define NSTAGE 3
#define NCHUNK 256            // stats chunk width = 32 cols

// smem: 3 stages of 4 tiles, each 128 rows x 144 bytes (128B data + 16B pad)
#define ROWB 144
#define TILE_B (128 * ROWB)        // 18432
#define S_AHI 0
#define S_ALO TILE_B
#define S_BHI (2 * TILE_B)
#define S_BLO (3 * TILE_B)
#define STAGE_B (4 * TILE_B)       // 73728
#define SMEM_LAB_A 0               // 128 ints
#define SMEM_LAB_B 512             // 128 ints
#define SMEM_STAGE0 1024
#define SMEM_TOTAL (SMEM_STAGE0 + NSTAGE * STAGE_B)   // 222208

// ---------------- device scratch (no cudaMalloc allowed) ----------------
__device__ __nv_bfloat16 gAhi[NN * DD];
__device__ __nv_bfloat16 gAlo[NN * DD];
__device__ __nv_bfloat16 gBhi[NN * DD];
__device__ __nv_bfloat16 gBlo[NN * DD];
__device__ float g_m [NCHUNK * NN];
__device__ float g_l [NCHUNK * NN];
__device__ float g_ms[NCHUNK * NN];
__device__ int   g_c [NCHUNK * NN];
__device__ int   g_lab[NN];

// ---------------- PTX helpers (baseline sm_80+ features only) ----------------
__device__ __forceinline__ uint32_t smem_u32(const void* p) {
    uint32_t a;
    asm("{ .reg .u64 t; cvta.to.shared.u64 t, %1; cvt.u32.u64 %0, t; }" : "=r"(a) : "l"(p));
    return a;
}
#define CPA16(dst, src) \
    asm volatile("cp.async.cg.shared.global [%0], [%1], 16;" :: "r"(dst), "l"(src))
#define CPA_COMMIT() asm volatile("cp.async.commit_group;" ::: "memory")
#define CPA_WAIT(n)  asm volatile("cp.async.wait_group %0;" :: "n"(n) : "memory")

__device__ __forceinline__ void ldsm4(uint32_t (&r)[4], uint32_t addr) {
    asm volatile("ldmatrix.sync.aligned.m8n8.x4.shared.b16 {%0,%1,%2,%3}, [%4];"
                 : "=r"(r[0]), "=r"(r[1]), "=r"(r[2]), "=r"(r[3]) : "r"(addr));
}
__device__ __forceinline__ void mma_bf16(float (&c)[4], const uint32_t (&a)[4],
                                         uint32_t b0, uint32_t b1) {
    asm volatile(
        "mma.sync.aligned.m16n8k16.row.col.f32.bf16.bf16.f32 "
        "{%0,%1,%2,%3}, {%4,%5,%6,%7}, {%8,%9}, {%0,%1,%2,%3};"
        : "+f"(c[0]), "+f"(c[1]), "+f"(c[2]), "+f"(c[3])
        : "r"(a[0]), "r"(a[1]), "r"(a[2]), "r"(a[3]), "r"(b0), "r"(b1));
}

// ---------------- label normalization (int32 vs int64 ambiguity) ----------------
__global__ void prep_labels(const void* __restrict__ labels_raw) {
    __shared__ int s_is64;
    if (threadIdx.x == 0) {
        const unsigned long long* p = (const unsigned long long*)labels_raw;
        int is64 = 1;
        for (int w = 0; w < 32; w++)
            if ((p[w] >> 32) != 0ull) { is64 = 0; break; }
        s_is64 = is64;
    }
    __syncthreads();
    const int is64 = s_is64;
    const long long* p64 = (const long long*)labels_raw;
    const int*       p32 = (const int*)labels_raw;
    for (int i = threadIdx.x; i < NN; i += blockDim.x)
        g_lab[i] = is64 ? (int)p64[i] : p32[i];
}

__global__ void zero_out(float* out) { if (threadIdx.x == 0) out[0] = 0.0f; }

// ---------------- fp32 -> bf16 hi/lo split ----------------
__global__ void split_bf16(const float* __restrict__ A, const float* __restrict__ B) {
    const int base = blockIdx.x * 256 + threadIdx.x;   // grid 2048 x 256
    #pragma unroll
    for (int i = 0; i < 4; i++) {
        int e = base + i * 524288;
        const float4* src;
        __nv_bfloat16 *hi, *lo;
        int off;
        if (e < 1048576) { src = (const float4*)A; off = e;           hi = gAhi; lo = gAlo; }
        else             { src = (const float4*)B; off = e - 1048576; hi = gBhi; lo = gBlo; }
        const float4 v = src[off];
        __nv_bfloat16 h0 = __float2bfloat16_rn(v.x);
        __nv_bfloat16 h1 = __float2bfloat16_rn(v.y);
        __nv_bfloat16 h2 = __float2bfloat16_rn(v.z);
        __nv_bfloat16 h3 = __float2bfloat16_rn(v.w);
        __nv_bfloat16 l0 = __float2bfloat16_rn(v.x - __bfloat162float(h0));
        __nv_bfloat16 l1 = __float2bfloat16_rn(v.y - __bfloat162float(h1));
        __nv_bfloat16 l2 = __float2bfloat16_rn(v.z - __bfloat162float(h2));
        __nv_bfloat16 l3 = __float2bfloat16_rn(v.w - __bfloat162float(h3));
        ((__nv_bfloat162*)hi)[off * 2 + 0] = __nv_bfloat162(h0, h1);
        ((__nv_bfloat162*)hi)[off * 2 + 1] = __nv_bfloat162(h2, h3);
        ((__nv_bfloat162*)lo)[off * 2 + 0] = __nv_bfloat162(l0, l1);
        ((__nv_bfloat162*)lo)[off * 2 + 1] = __nv_bfloat162(l2, l3);
    }
}

// ---------------- GEMM building blocks ----------------
__device__ __forceinline__ void load_stage(uint32_t sbase, int slot, int ki,
                                           int by, int bx, int tid) {
    const uint32_t stg = sbase + SMEM_STAGE0 + slot * STAGE_B;
    const int kb = ki * 128;          // byte offset within a 1024B feature row
    #pragma unroll
    for (int j = 0; j < 2; j++) {
        const int c = tid + j * 512;  // 0..1023
        const int r = c >> 3, q = c & 7;
        const uint32_t so = (uint32_t)(r * ROWB + q * 16);
        const size_t gA = (size_t)(by * BM + r) * 1024 + kb + q * 16;
        const size_t gB = (size_t)(bx * BN + r) * 1024 + kb + q * 16;
        CPA16(stg + S_AHI + so, (const char*)gAhi + gA);
        CPA16(stg + S_ALO + so, (const char*)gAlo + gA);
        CPA16(stg + S_BHI + so, (const char*)gBhi + gB);
        CPA16(stg + S_BLO + so, (const char*)gBlo + gB);
    }
}

// Warp tile 32(M) x 32(N); 4 k16-steps per stage.
// The three emulation passes are issued as SEPARATE loops so each accumulator's
// dependent MMAs are 8 instructions apart (breaks the RAW chain that capped
// tensor-pipe issue at 1/14.5 cyc).
__device__ __forceinline__ void compute_stage(uint32_t stg, int wm, int wn, int lane,
                                              float (&acc)[2][4][4]) {
    #pragma unroll
    for (int ks = 0; ks < 4; ks++) {
        uint32_t ah[2][4], al[2][4], bh[2][4], bl[2][4];
        const uint32_t a_lane = (uint32_t)((wm * 32 + (lane & 15)) * ROWB +
                                           ((lane >> 4) << 4) + ks * 32);
        #pragma unroll
        for (int mt = 0; mt < 2; mt++) {
            const uint32_t ad = stg + S_AHI + a_lane + mt * 16 * ROWB;
            ldsm4(ah[mt], ad);
            ldsm4(al[mt], ad + (S_ALO - S_AHI));
        }
        const uint32_t b_lane = (uint32_t)((wn * 32 + ((lane >> 4) & 1) * 8 + (lane & 7)) * ROWB +
                                           (((lane >> 3) & 1) << 4) + ks * 32);
        #pragma unroll
        for (int ntp = 0; ntp < 2; ntp++) {
            const uint32_t bd = stg + S_BHI + b_lane + ntp * 16 * ROWB;
            ldsm4(bh[ntp], bd);
            ldsm4(bl[ntp], bd + (S_BLO - S_BHI));
        }
        // pass 1: hi * hi (8 independent MMAs)
        #pragma unroll
        for (int mt = 0; mt < 2; mt++)
            #pragma unroll
            for (int nt = 0; nt < 4; nt++) {
                const int ntp = nt >> 1, s2 = (nt & 1) * 2;
                mma_bf16(acc[mt][nt], ah[mt], bh[ntp][s2], bh[ntp][s2 + 1]);
            }
        // pass 2: hi * lo
        #pragma unroll
        for (int mt = 0; mt < 2; mt++)
            #pragma unroll
            for (int nt = 0; nt < 4; nt++) {
                const int ntp = nt >> 1, s2 = (nt & 1) * 2;
                mma_bf16(acc[mt][nt], ah[mt], bl[ntp][s2], bl[ntp][s2 + 1]);
            }
        // pass 3: lo * hi
        #pragma unroll
        for (int mt = 0; mt < 2; mt++)
            #pragma unroll
            for (int nt = 0; nt < 4; nt++) {
                const int ntp = nt >> 1, s2 = (nt & 1) * 2;
                mma_bf16(acc[mt][nt], al[mt], bh[ntp][s2], bh[ntp][s2 + 1]);
            }
    }
}

// ---------------- fused GEMM + stats ----------------
__global__ void __launch_bounds__(NTHREADS, 1)
gemm_mma(const float* __restrict__ scale_p)
{
    extern __shared__ char smem[];
    const uint32_t sbase = smem_u32(smem);
    const int tid = threadIdx.x;
    const int wid = tid >> 5, lane = tid & 31;
    const int wm = wid >> 2, wn = wid & 3;      // 4x4 warp grid, tile 32x32
    const int bx = blockIdx.x, by = blockIdx.y;

    int* labA = (int*)(smem + SMEM_LAB_A);
    int* labB = (int*)(smem + SMEM_LAB_B);
    if (tid < 128)                     labA[tid] = g_lab[by * BM + tid];
    else if (tid < 256)                labB[tid - 128] = g_lab[bx * BN + (tid - 128)];

    // prologue: 2 stages in flight
    load_stage(sbase, 0, 0, by, bx, tid); CPA_COMMIT();
    load_stage(sbase, 1, 1, by, bx, tid); CPA_COMMIT();

    float acc[2][4][4];
    #pragma unroll
    for (int a = 0; a < 2; a++)
        #pragma unroll
        for (int b = 0; b < 4; b++)
            #pragma unroll
            for (int e = 0; e < 4; e++) acc[a][b][e] = 0.0f;

    // single-sync 3-stage pipeline
    #pragma unroll 1
    for (int i = 0; i < NKITER; i++) {
        if (i < NKITER - 1) CPA_WAIT(1);
        else                CPA_WAIT(0);
        __syncthreads();
        if (i + 2 < NKITER) { load_stage(sbase, (i + 2) % NSTAGE, i + 2, by, bx, tid); CPA_COMMIT(); }
        compute_stage(sbase + SMEM_STAGE0 + (i % NSTAGE) * STAGE_B, wm, wn, lane, acc);
    }

    // ---------------- epilogue: per-row stats over this warp's 32 columns ----------------
    const float s = *scale_p;
    const int chunk = bx * 4 + wn;
    const int colb = bx * BN + wn * 32 + (lane & 3) * 2;

    #pragma unroll
    for (int mt = 0; mt < 2; mt++) {
        #pragma unroll
        for (int half = 0; half < 2; half++) {
            const int rloc = wm * 32 + mt * 16 + (lane >> 2) + half * 8;
            const int gy = by * BM + rloc;
            const int labr = labA[rloc];

            float v[8];
            #pragma unroll
            for (int nt = 0; nt < 4; nt++) {
                v[nt * 2 + 0] = acc[mt][nt][half * 2 + 0] * s;
                v[nt * 2 + 1] = acc[mt][nt][half * 2 + 1] * s;
            }
            float m = v[0];
            #pragma unroll
            for (int j = 1; j < 8; j++) m = fmaxf(m, v[j]);
            m = fmaxf(m, __shfl_xor_sync(0xffffffffu, m, 1));
            m = fmaxf(m, __shfl_xor_sync(0xffffffffu, m, 2));

            float l = 0.0f, msum = 0.0f;
            int cnt = 0;
            #pragma unroll
            for (int j = 0; j < 8; j++) {
                l += __expf(v[j] - m);
                const int gx = colb + (j >> 1) * 8 + (j & 1);
                const int cloc = wn * 32 + (j >> 1) * 8 + (lane & 3) * 2 + (j & 1);
                if (labB[cloc] == labr && gx != gy) { msum += v[j]; cnt++; }
            }
            l    += __shfl_xor_sync(0xffffffffu, l, 1);
            l    += __shfl_xor_sync(0xffffffffu, l, 2);
            msum += __shfl_xor_sync(0xffffffffu, msum, 1);
            msum += __shfl_xor_sync(0xffffffffu, msum, 2);
            cnt  += __shfl_xor_sync(0xffffffffu, cnt, 1);
            cnt  += __shfl_xor_sync(0xffffffffu, cnt, 2);

            if ((lane & 3) == 0) {
                const int idx = chunk * NN + gy;
                g_m[idx] = m; g_l[idx] = l; g_ms[idx] = msum; g_c[idx] = cnt;
            }
        }
    }
}

// ---------------- chunk merge + final loss ----------------
__global__ void reduce_rows(float* __restrict__ out)
{
    const int t = blockIdx.x * 256 + threadIdx.x;   // 65536 threads
    const int row = t >> 3;
    const int sub = t & 7;                          // 8 lanes per row, 32 chunks each
    const int c0 = sub * 32;

    float M = -CUDART_INF_F;
    #pragma unroll 8
    for (int c = 0; c < 32; c++)
        M = fmaxf(M, g_m[(c0 + c) * NN + row]);
    #pragma unroll
    for (int o = 1; o <= 4; o <<= 1)
        M = fmaxf(M, __shfl_xor_sync(0xffffffffu, M, o));

    float L = 0.0f, MS = 0.0f;
    int C = 0;
    #pragma unroll 8
    for (int c = 0; c < 32; c++) {
        const int i = (c0 + c) * NN + row;
        L  += g_l[i] * __expf(g_m[i] - M);
        MS += g_ms[i];
        C  += g_c[i];
    }
    #pragma unroll
    for (int o = 1; o <= 4; o <<= 1) {
        L  += __shfl_xor_sync(0xffffffffu, L,  o);
        MS += __shfl_xor_sync(0xffffffffu, MS, o);
        C  += __shfl_xor_sync(0xffffffffu, C,  o);
    }

    float val = 0.0f;
    if (sub == 0) {
        const float lse = M + logf(L);
        val = (C > 0) ? (MS / (float)C - lse) : 0.0f;
    }
    #pragma unroll
    for (int o = 16; o >= 1; o >>= 1)
        val += __shfl_xor_sync(0xffffffffu, val, o);

    __shared__ float sred[8];
    if ((threadIdx.x & 31) == 0) sred[threadIdx.x >> 5] = val;
    __syncthreads();
    if (threadIdx.x == 0) {
        float tsum = 0.0f;
        #pragma unroll
        for (int w = 0; w < 8; w++) tsum += sred[w];
        atomicAdd(out, -tsum / (float)NN);
    }
}

// ---------------- launch ----------------
extern "C" void kernel_launch(void* const* d_in, const int* in_sizes, int n_in,
                              void* d_out, int out_size)
{
    const float* image  = (const float*)d_in[0];
    const float* text   = (const float*)d_in[1];
    const float* scale  = (const float*)d_in[2];
    const void*  labels = d_in[3];
    float* out = (float*)d_out;

    cudaFuncSetAttribute(gemm_mma, cudaFuncAttributeMaxDynamicSharedMemorySize, SMEM_TOTAL);

    prep_labels<<<1, 256>>>(labels);
    zero_out<<<1, 32>>>(out);
    split_bf16<<<2048, 256>>>(image, text);

    dim3 grid(NN / BN, NN / BM);   // 64 x 64 tiles
    gemm_mma<<<grid, NTHREADS, SMEM_TOTAL>>>(scale);

    reduce_rows<<<256, 256>>>(out);
}

// round 6
// speedup vs baseline: 6.5793x; 2.6318x over previous
#include <cuda_runtime.h>
#include <cuda_bf16.h>
#include <math_constants.h>
#include <cstdint>

// Problem shape (fixed by the reference)
#define NN 8192
#define DD 512

// GEMM tiling
#define BM 128
#define BN 128
#define BK 64                 // bf16 elements per smem stage
#define NKITER (DD / BK)      // 8
#define NTHREADS 256
#define NSTAGE 3
#define NCHUNK 256            // stats chunk width = 32 cols

// smem: 3 stages of 2 tiles (A,B), each 128 rows x 144 bytes (128B data + 16B pad)
#define ROWB 144
#define TILE_B (128 * ROWB)        // 18432
#define S_A 0
#define S_B TILE_B
#define STAGE_B (2 * TILE_B)       // 36864
#define SMEM_LAB_A 0               // 128 ints
#define SMEM_LAB_B 512             // 128 ints
#define SMEM_STAGE0 1024
#define SMEM_TOTAL (SMEM_STAGE0 + NSTAGE * STAGE_B)   // 111616 (2 CTAs/SM)

// ---------------- device scratch (no cudaMalloc allowed) ----------------
__device__ __nv_bfloat16 gA[NN * DD];
__device__ __nv_bfloat16 gB[NN * DD];
__device__ float g_m [NCHUNK * NN];
__device__ float g_l [NCHUNK * NN];
__device__ float g_ms[NCHUNK * NN];
__device__ int   g_c [NCHUNK * NN];
__device__ int   g_lab[NN];

// ---------------- PTX helpers (baseline sm_80+ features only) ----------------
__device__ __forceinline__ uint32_t smem_u32(const void* p) {
    uint32_t a;
    asm("{ .reg .u64 t; cvta.to.shared.u64 t, %1; cvt.u32.u64 %0, t; }" : "=r"(a) : "l"(p));
    return a;
}
#define CPA16(dst, src) \
    asm volatile("cp.async.cg.shared.global [%0], [%1], 16;" :: "r"(dst), "l"(src))
#define CPA_COMMIT() asm volatile("cp.async.commit_group;" ::: "memory")
#define CPA_WAIT(n)  asm volatile("cp.async.wait_group %0;" :: "n"(n) : "memory")

__device__ __forceinline__ void ldsm4(uint32_t (&r)[4], uint32_t addr) {
    asm volatile("ldmatrix.sync.aligned.m8n8.x4.shared.b16 {%0,%1,%2,%3}, [%4];"
                 : "=r"(r[0]), "=r"(r[1]), "=r"(r[2]), "=r"(r[3]) : "r"(addr));
}
__device__ __forceinline__ void mma_bf16(float (&c)[4], const uint32_t (&a)[4],
                                         uint32_t b0, uint32_t b1) {
    asm volatile(
        "mma.sync.aligned.m16n8k16.row.col.f32.bf16.bf16.f32 "
        "{%0,%1,%2,%3}, {%4,%5,%6,%7}, {%8,%9}, {%0,%1,%2,%3};"
        : "+f"(c[0]), "+f"(c[1]), "+f"(c[2]), "+f"(c[3])
        : "r"(a[0]), "r"(a[1]), "r"(a[2]), "r"(a[3]), "r"(b0), "r"(b1));
}

// ---------------- label normalization (int32 vs int64 ambiguity) ----------------
__global__ void prep_labels(const void* __restrict__ labels_raw) {
    __shared__ int s_is64;
    if (threadIdx.x == 0) {
        const unsigned long long* p = (const unsigned long long*)labels_raw;
        int is64 = 1;
        for (int w = 0; w < 32; w++)
            if ((p[w] >> 32) != 0ull) { is64 = 0; break; }
        s_is64 = is64;
    }
    __syncthreads();
    const int is64 = s_is64;
    const long long* p64 = (const long long*)labels_raw;
    const int*       p32 = (const int*)labels_raw;
    for (int i = threadIdx.x; i < NN; i += blockDim.x)
        g_lab[i] = is64 ? (int)p64[i] : p32[i];
}

__global__ void zero_out(float* out) { if (threadIdx.x == 0) out[0] = 0.0f; }

// ---------------- fp32 -> bf16 convert (single precision level) ----------------
__global__ void cvt_bf16(const float* __restrict__ A, const float* __restrict__ B) {
    const int base = blockIdx.x * 256 + threadIdx.x;   // grid 2048 x 256
    #pragma unroll
    for (int i = 0; i < 4; i++) {
        int e = base + i * 524288;                     // 2 * 1048576 float4 total
        const float4* src;
        __nv_bfloat16* dst;
        int off;
        if (e < 1048576) { src = (const float4*)A; off = e;           dst = gA; }
        else             { src = (const float4*)B; off = e - 1048576; dst = gB; }
        const float4 v = src[off];
        ((__nv_bfloat162*)dst)[off * 2 + 0] =
            __nv_bfloat162(__float2bfloat16_rn(v.x), __float2bfloat16_rn(v.y));
        ((__nv_bfloat162*)dst)[off * 2 + 1] =
            __nv_bfloat162(__float2bfloat16_rn(v.z), __float2bfloat16_rn(v.w));
    }
}

// ---------------- GEMM building blocks ----------------
// Stage load: 2 tiles of 128 rows x 128B = 2048 x 16B chunks, 256 threads ->
// 4 chunks per thread per tile.
__device__ __forceinline__ void load_stage(uint32_t sbase, int slot, int ki,
                                           int by, int bx, int tid) {
    const uint32_t stg = sbase + SMEM_STAGE0 + slot * STAGE_B;
    const int kb = ki * 128;          // byte offset within a 1024B feature row
    #pragma unroll
    for (int j = 0; j < 4; j++) {
        const int c = tid + j * 256;  // 0..1023
        const int r = c >> 3, q = c & 7;
        const uint32_t so = (uint32_t)(r * ROWB + q * 16);
        const size_t gAo = (size_t)(by * BM + r) * 1024 + kb + q * 16;
        const size_t gBo = (size_t)(bx * BN + r) * 1024 + kb + q * 16;
        CPA16(stg + S_A + so, (const char*)gA + gAo);
        CPA16(stg + S_B + so, (const char*)gB + gBo);
    }
}

// Warp tile 64(M) x 32(N); 4 k16-steps per stage; 16 MMA per ks.
__device__ __forceinline__ void compute_stage(uint32_t stg, int wm, int wn, int lane,
                                              float (&acc)[4][4][4]) {
    #pragma unroll
    for (int ks = 0; ks < 4; ks++) {
        uint32_t a[4][4], b[2][4];
        const uint32_t a_lane = (uint32_t)((wm * 64 + (lane & 15)) * ROWB +
                                           ((lane >> 4) << 4) + ks * 32);
        #pragma unroll
        for (int mt = 0; mt < 4; mt++)
            ldsm4(a[mt], stg + S_A + a_lane + mt * 16 * ROWB);
        const uint32_t b_lane = (uint32_t)((wn * 32 + ((lane >> 4) & 1) * 8 + (lane & 7)) * ROWB +
                                           (((lane >> 3) & 1) << 4) + ks * 32);
        #pragma unroll
        for (int ntp = 0; ntp < 2; ntp++)
            ldsm4(b[ntp], stg + S_B + b_lane + ntp * 16 * ROWB);
        #pragma unroll
        for (int mt = 0; mt < 4; mt++)
            #pragma unroll
            for (int nt = 0; nt < 4; nt++) {
                const int ntp = nt >> 1, s2 = (nt & 1) * 2;
                mma_bf16(acc[mt][nt], a[mt], b[ntp][s2], b[ntp][s2 + 1]);
            }
    }
}

// ---------------- fused GEMM + stats ----------------
__global__ void __launch_bounds__(NTHREADS, 2)
gemm_mma(const float* __restrict__ scale_p)
{
    extern __shared__ char smem[];
    const uint32_t sbase = smem_u32(smem);
    const int tid = threadIdx.x;
    const int wid = tid >> 5, lane = tid & 31;
    const int wm = wid >> 2, wn = wid & 3;      // 2x4 warp grid, tile 64x32
    const int bx = blockIdx.x, by = blockIdx.y;

    int* labA = (int*)(smem + SMEM_LAB_A);
    int* labB = (int*)(smem + SMEM_LAB_B);
    if (tid < 128)       labA[tid] = g_lab[by * BM + tid];
    else                 labB[tid - 128] = g_lab[bx * BN + (tid - 128)];

    // prologue: 2 stages in flight
    load_stage(sbase, 0, 0, by, bx, tid); CPA_COMMIT();
    load_stage(sbase, 1, 1, by, bx, tid); CPA_COMMIT();

    float acc[4][4][4];
    #pragma unroll
    for (int a = 0; a < 4; a++)
        #pragma unroll
        for (int b = 0; b < 4; b++)
            #pragma unroll
            for (int e = 0; e < 4; e++) acc[a][b][e] = 0.0f;

    // single-sync 3-stage pipeline
    #pragma unroll 1
    for (int i = 0; i < NKITER; i++) {
        if (i < NKITER - 1) CPA_WAIT(1);
        else                CPA_WAIT(0);
        __syncthreads();
        if (i + 2 < NKITER) { load_stage(sbase, (i + 2) % NSTAGE, i + 2, by, bx, tid); CPA_COMMIT(); }
        compute_stage(sbase + SMEM_STAGE0 + (i % NSTAGE) * STAGE_B, wm, wn, lane, acc);
    }

    // ---------------- epilogue: per-row stats over this warp's 32 columns ----------------
    const float s = *scale_p;
    const int chunk = bx * 4 + wn;
    const int colb = bx * BN + wn * 32 + (lane & 3) * 2;

    #pragma unroll
    for (int mt = 0; mt < 4; mt++) {
        #pragma unroll
        for (int half = 0; half < 2; half++) {
            const int rloc = wm * 64 + mt * 16 + (lane >> 2) + half * 8;
            const int gy = by * BM + rloc;
            const int labr = labA[rloc];

            float v[8];
            #pragma unroll
            for (int nt = 0; nt < 4; nt++) {
                v[nt * 2 + 0] = acc[mt][nt][half * 2 + 0] * s;
                v[nt * 2 + 1] = acc[mt][nt][half * 2 + 1] * s;
            }
            float m = v[0];
            #pragma unroll
            for (int j = 1; j < 8; j++) m = fmaxf(m, v[j]);
            m = fmaxf(m, __shfl_xor_sync(0xffffffffu, m, 1));
            m = fmaxf(m, __shfl_xor_sync(0xffffffffu, m, 2));

            float l = 0.0f, msum = 0.0f;
            int cnt = 0;
            #pragma unroll
            for (int j = 0; j < 8; j++) {
                l += __expf(v[j] - m);
                const int gx = colb + (j >> 1) * 8 + (j & 1);
                const int cloc = wn * 32 + (j >> 1) * 8 + (lane & 3) * 2 + (j & 1);
                if (labB[cloc] == labr && gx != gy) { msum += v[j]; cnt++; }
            }
            l    += __shfl_xor_sync(0xffffffffu, l, 1);
            l    += __shfl_xor_sync(0xffffffffu, l, 2);
            msum += __shfl_xor_sync(0xffffffffu, msum, 1);
            msum += __shfl_xor_sync(0xffffffffu, msum, 2);
            cnt  += __shfl_xor_sync(0xffffffffu, cnt, 1);
            cnt  += __shfl_xor_sync(0xffffffffu, cnt, 2);

            if ((lane & 3) == 0) {
                const int idx = chunk * NN + gy;
                g_m[idx] = m; g_l[idx] = l; g_ms[idx] = msum; g_c[idx] = cnt;
            }
        }
    }
}

// ---------------- chunk merge + final loss ----------------
__global__ void reduce_rows(float* __restrict__ out)
{
    const int t = blockIdx.x * 256 + threadIdx.x;   // 65536 threads
    const int row = t >> 3;
    const int sub = t & 7;                          // 8 lanes per row, 32 chunks each
    const int c0 = sub * 32;

    float M = -CUDART_INF_F;
    #pragma unroll 8
    for (int c = 0; c < 32; c++)
        M = fmaxf(M, g_m[(c0 + c) * NN + row]);
    #pragma unroll
    for (int o = 1; o <= 4; o <<= 1)
        M = fmaxf(M, __shfl_xor_sync(0xffffffffu, M, o));

    float L = 0.0f, MS = 0.0f;
    int C = 0;
    #pragma unroll 8
    for (int c = 0; c < 32; c++) {
        const int i = (c0 + c) * NN + row;
        L  += g_l[i] * __expf(g_m[i] - M);
        MS += g_ms[i];
        C  += g_c[i];
    }
    #pragma unroll
    for (int o = 1; o <= 4; o <<= 1) {
        L  += __shfl_xor_sync(0xffffffffu, L,  o);
        MS += __shfl_xor_sync(0xffffffffu, MS, o);
        C  += __shfl_xor_sync(0xffffffffu, C,  o);
    }

    float val = 0.0f;
    if (sub == 0) {
        const float lse = M + logf(L);
        val = (C > 0) ? (MS / (float)C - lse) : 0.0f;
    }
    #pragma unroll
    for (int o = 16; o >= 1; o >>= 1)
        val += __shfl_xor_sync(0xffffffffu, val, o);

    __shared__ float sred[8];
    if ((threadIdx.x & 31) == 0) sred[threadIdx.x >> 5] = val;
    __syncthreads();
    if (threadIdx.x == 0) {
        float tsum = 0.0f;
        #pragma unroll
        for (int w = 0; w < 8; w++) tsum += sred[w];
        atomicAdd(out, -tsum / (float)NN);
    }
}

// ---------------- launch ----------------
extern "C" void kernel_launch(void* const* d_in, const int* in_sizes, int n_in,
                              void* d_out, int out_size)
{
    const float* image  = (const float*)d_in[0];
    const float* text   = (const float*)d_in[1];
    const float* scale  = (const float*)d_in[2];
    const void*  labels = d_in[3];
    float* out = (float*)d_out;

    cudaFuncSetAttribute(gemm_mma, cudaFuncAttributeMaxDynamicSharedMemorySize, SMEM_TOTAL);

    prep_labels<<<1, 256>>>(labels);
    zero_out<<<1, 32>>>(out);
    cvt_bf16<<<2048, 256>>>(image, text);

    dim3 grid(NN / BN, NN / BM);   // 64 x 64 tiles
    gemm_mma<<<grid, NTHREADS, SMEM_TOTAL>>>(scale);

    reduce_rows<<<256, 256>>>(out);
}